// round 1
// baseline (speedup 1.0000x reference)
#include <cuda_runtime.h>
#include <cstdint>

#define N_NODES 50000
#define N_EDGES 800000
#define DIM     64
#define NLAYERS 3

// Scratch buffers (no cudaMalloc allowed). 3 x 12.8 MB.
__device__ float g_bufA[N_NODES * DIM];
__device__ float g_bufB[N_NODES * DIM];
__device__ float g_agg [N_NODES * DIM];

// ---------------------------------------------------------------------------
// Zero the aggregation buffer (agg is L2-resident; ~12.8MB)
// ---------------------------------------------------------------------------
__global__ void zero_kernel(float4* __restrict__ p, int n4) {
    int i = blockIdx.x * blockDim.x + threadIdx.x;
    if (i < n4) p[i] = make_float4(0.f, 0.f, 0.f, 0.f);
}

// ---------------------------------------------------------------------------
// Scatter: agg[dst] += ew * h[src]. 16 threads per edge, one float4 each.
// Uses 128-bit vector reduction (red.global.add.v4.f32, sm_90+) to quarter
// the L2 atomic op count vs scalar atomicAdd.
// ---------------------------------------------------------------------------
__global__ __launch_bounds__(256) void scatter_kernel(
    const float4* __restrict__ h,
    const int*    __restrict__ src,
    const int*    __restrict__ dst,
    const float*  __restrict__ ew,
    float4*       __restrict__ agg)
{
    int t = blockIdx.x * blockDim.x + threadIdx.x;
    int e = t >> 4;
    if (e >= N_EDGES) return;
    int lane = t & 15;

    int   s = __ldg(src + e);
    int   d = __ldg(dst + e);
    float w = __ldg(ew  + e);

    float4 v = __ldg(h + (size_t)s * 16 + lane);
    float4* p = agg + (size_t)d * 16 + lane;
    asm volatile("red.global.add.v4.f32 [%0], {%1,%2,%3,%4};"
                 :: "l"(p), "f"(v.x * w), "f"(v.y * w), "f"(v.z * w), "f"(v.w * w)
                 : "memory");
}

// ---------------------------------------------------------------------------
// Fused dual GEMM: out[r][c] = sum_k H[r][k]*Wroot[k][c]
//                            + sum_k AGG[r][k]*Wrel[k][c] + bias[c]
// (optionally tanh). Treated as [H|AGG] (K=128) @ [Wroot;Wrel].
//
// Block: 256 threads, 64-row x 64-col output tile, each thread 4x4 outputs.
// W_cat (128x64 f32 = 32KB) staged in SMEM once per block; A staged in
// 16-wide K chunks, stored transposed so the compute loop uses LDS.128.
// ---------------------------------------------------------------------------
__global__ __launch_bounds__(256) void gemm_kernel(
    const float* __restrict__ H,
    const float* __restrict__ AGG,
    const float* __restrict__ Wroot,   // [64][64]
    const float* __restrict__ Wrel,    // [64][64]
    const float* __restrict__ bias,    // [64]
    float*       __restrict__ out,
    int doTanh)
{
    __shared__ float Ws[128][64];   // k<64: Wroot, k>=64: Wrel
    __shared__ float As[16][68];    // [kk][row], padded

    const int tid = threadIdx.x;
    const int ty  = tid >> 4;       // 0..15 -> row group (4 rows)
    const int tx  = tid & 15;       // 0..15 -> col group (4 cols)
    const int rowBase = blockIdx.x * 64;

    // Stage W_cat: 8192 floats / 256 threads = 8 float4 per thread
    #pragma unroll
    for (int it = 0; it < 8; it++) {
        int f4 = tid + it * 256;        // 0..2047
        int k  = f4 >> 4;               // 0..127
        int jq = f4 & 15;               // 0..15
        const float* srcw = (k < 64) ? (Wroot + k * 64 + jq * 4)
                                     : (Wrel + (k - 64) * 64 + jq * 4);
        float4 wv = __ldg((const float4*)srcw);
        *(float4*)&Ws[k][jq * 4] = wv;
    }

    float acc[4][4];
    #pragma unroll
    for (int i = 0; i < 4; i++)
        #pragma unroll
        for (int j = 0; j < 4; j++) acc[i][j] = 0.f;

    const int ldRow   = tid >> 2;        // 0..63
    const int ldKpart = (tid & 3) * 4;   // 0,4,8,12
    const int gRow    = rowBase + ldRow;
    const bool rowOk  = (gRow < N_NODES);

    #pragma unroll 1
    for (int kc = 0; kc < 8; kc++) {
        __syncthreads();
        // Stage A chunk (64 rows x 16 k), transposed store.
        const float* srcA = (kc < 4) ? H : AGG;
        int kLocal = (kc & 3) * 16 + ldKpart;
        float4 av = make_float4(0.f, 0.f, 0.f, 0.f);
        if (rowOk) av = __ldg((const float4*)(srcA + (size_t)gRow * 64 + kLocal));
        As[ldKpart + 0][ldRow] = av.x;
        As[ldKpart + 1][ldRow] = av.y;
        As[ldKpart + 2][ldRow] = av.z;
        As[ldKpart + 3][ldRow] = av.w;
        __syncthreads();

        #pragma unroll
        for (int kk = 0; kk < 16; kk++) {
            float4 a = *(const float4*)&As[kk][ty * 4];
            float4 b = *(const float4*)&Ws[kc * 16 + kk][tx * 4];
            acc[0][0] += a.x * b.x; acc[0][1] += a.x * b.y;
            acc[0][2] += a.x * b.z; acc[0][3] += a.x * b.w;
            acc[1][0] += a.y * b.x; acc[1][1] += a.y * b.y;
            acc[1][2] += a.y * b.z; acc[1][3] += a.y * b.w;
            acc[2][0] += a.z * b.x; acc[2][1] += a.z * b.y;
            acc[2][2] += a.z * b.z; acc[2][3] += a.z * b.w;
            acc[3][0] += a.w * b.x; acc[3][1] += a.w * b.y;
            acc[3][2] += a.w * b.z; acc[3][3] += a.w * b.w;
        }
    }

    float4 bv = __ldg((const float4*)(bias + tx * 4));

    #pragma unroll
    for (int i = 0; i < 4; i++) {
        int r = rowBase + ty * 4 + i;
        if (r >= N_NODES) break;
        float4 o;
        o.x = acc[i][0] + bv.x;
        o.y = acc[i][1] + bv.y;
        o.z = acc[i][2] + bv.z;
        o.w = acc[i][3] + bv.w;
        if (doTanh) {
            o.x = tanhf(o.x); o.y = tanhf(o.y);
            o.z = tanhf(o.z); o.w = tanhf(o.w);
        }
        *(float4*)(out + (size_t)r * 64 + tx * 4) = o;
    }
}

// ---------------------------------------------------------------------------
// Launcher
// ---------------------------------------------------------------------------
extern "C" void kernel_launch(void* const* d_in, const int* in_sizes, int n_in,
                              void* d_out, int out_size)
{
    const float* x      = (const float*)d_in[0];   // [N, 64]
    const int*   eidx   = (const int*)  d_in[1];   // [2, E]
    const float* ew     = (const float*)d_in[2];   // [E]
    const float* W_rel  = (const float*)d_in[3];   // [L, 64, 64]
    const float* b_rel  = (const float*)d_in[4];   // [L, 64]
    const float* W_root = (const float*)d_in[5];   // [L, 64, 64]
    float* out = (float*)d_out;

    const int* src = eidx;            // row 0
    const int* dst = eidx + N_EDGES;  // row 1

    float *pA, *pB, *pAgg;
    cudaGetSymbolAddress((void**)&pA,   g_bufA);
    cudaGetSymbolAddress((void**)&pB,   g_bufB);
    cudaGetSymbolAddress((void**)&pAgg, g_agg);

    const int n4 = N_NODES * (DIM / 4);              // float4 count = 800000
    const int zeroBlocks    = (n4 + 255) / 256;
    const int scatterBlocks = (N_EDGES * 16 + 255) / 256;
    const int gemmBlocks    = (N_NODES + 63) / 64;

    const float* hprev = x;
    for (int layer = 0; layer < NLAYERS; layer++) {
        float* hnext = (layer == NLAYERS - 1) ? out : ((layer == 0) ? pA : pB);

        zero_kernel<<<zeroBlocks, 256>>>((float4*)pAgg, n4);
        scatter_kernel<<<scatterBlocks, 256>>>(
            (const float4*)hprev, src, dst, ew, (float4*)pAgg);
        gemm_kernel<<<gemmBlocks, 256>>>(
            hprev, pAgg,
            W_root + (size_t)layer * DIM * DIM,
            W_rel  + (size_t)layer * DIM * DIM,
            b_rel  + (size_t)layer * DIM,
            hnext,
            layer == NLAYERS - 1 ? 1 : 0);

        hprev = hnext;
    }
}